// round 2
// baseline (speedup 1.0000x reference)
#include <cuda_runtime.h>
#include <cuda_bf16.h>
#include <cstdint>
#include <cstddef>
#include <math.h>

#define BATCH  256
#define HCLK   200
#define NCAND  64
#define DMODEL 640
#define NHEADS 10
#define HDIM   64
#define MROWS_K (BATCH*HCLK)
#define MROWS_Q (BATCH*NCAND)

__device__ __nv_bfloat16 g_Qbf[(size_t)MROWS_Q*DMODEL];
__device__ __nv_bfloat16 g_Kbf[(size_t)MROWS_K*DMODEL];
__device__ float         g_X  [(size_t)MROWS_K*DMODEL];
__device__ float         g_qw [MROWS_Q];
__device__ float         g_aggp[(size_t)BATCH*NHEADS*HCLK];
__device__ float         g_aw [MROWS_K];

#define BM 128
#define BN 128
#define BKD 32
#define TSTR 40

#define MMA_BF16(d, a, b) \
  asm volatile( \
    "mma.sync.aligned.m16n8k16.row.col.f32.bf16.bf16.f32 " \
    "{%0,%1,%2,%3}, {%4,%5,%6,%7}, {%8,%9}, {%0,%1,%2,%3};\n" \
    : "+f"((d)[0]), "+f"((d)[1]), "+f"((d)[2]), "+f"((d)[3]) \
    : "r"((a)[0]), "r"((a)[1]), "r"((a)[2]), "r"((a)[3]), \
      "r"((b)[0]), "r"((b)[1]))

// C[M,640] = A[M,K] @ W[640,K]^T (+bias). MODE: 0->g_Kbf, 1->g_Qbf (bf16,+bias), 2->g_X (fp32)
template<int MODE>
__global__ __launch_bounds__(256)
void gemm_kernel(const float* __restrict__ A, const float* __restrict__ W,
                 const float* __restrict__ bias, int M, int K)
{
    __shared__ __nv_bfloat16 As[BM*TSTR];
    __shared__ __nv_bfloat16 Bs[BN*TSTR];
    const int tid = threadIdx.x;
    const int bn0 = blockIdx.x * BN, bm0 = blockIdx.y * BM;
    const int warp = tid >> 5, lane = tid & 31;
    const int wm = warp & 3, wn = warp >> 2;
    const int g = lane >> 2, tig = lane & 3;

    float acc[2][8][4];
    #pragma unroll
    for (int i = 0; i < 2; i++)
      #pragma unroll
      for (int j = 0; j < 8; j++)
        #pragma unroll
        for (int v = 0; v < 4; v++) acc[i][j][v] = 0.f;

    for (int kb = 0; kb < K/BKD; kb++) {
        const int k0 = kb * BKD;
        #pragma unroll
        for (int it = 0; it < 4; it++) {
            int idx = tid + it*256;
            int r = idx >> 3, c4 = (idx & 7) << 2;
            float4 va = *(const float4*)(A + (size_t)(bm0 + r)*K + k0 + c4);
            *(__nv_bfloat162*)(&As[r*TSTR + c4])   = __floats2bfloat162_rn(va.x, va.y);
            *(__nv_bfloat162*)(&As[r*TSTR + c4+2]) = __floats2bfloat162_rn(va.z, va.w);
            float4 vb = *(const float4*)(W + (size_t)(bn0 + r)*K + k0 + c4);
            *(__nv_bfloat162*)(&Bs[r*TSTR + c4])   = __floats2bfloat162_rn(vb.x, vb.y);
            *(__nv_bfloat162*)(&Bs[r*TSTR + c4+2]) = __floats2bfloat162_rn(vb.z, vb.w);
        }
        __syncthreads();
        #pragma unroll
        for (int ks = 0; ks < 2; ks++) {
            const int kk = ks*16 + 2*tig;
            uint32_t afr[2][4];
            #pragma unroll
            for (int i = 0; i < 2; i++) {
                const __nv_bfloat16* p = &As[(wm*32 + i*16 + g)*TSTR + kk];
                afr[i][0] = *(const uint32_t*)(p);
                afr[i][1] = *(const uint32_t*)(p + 8*TSTR);
                afr[i][2] = *(const uint32_t*)(p + 8);
                afr[i][3] = *(const uint32_t*)(p + 8*TSTR + 8);
            }
            uint32_t bfr[8][2];
            #pragma unroll
            for (int j = 0; j < 8; j++) {
                const __nv_bfloat16* p = &Bs[(wn*64 + j*8 + g)*TSTR + kk];
                bfr[j][0] = *(const uint32_t*)(p);
                bfr[j][1] = *(const uint32_t*)(p + 8);
            }
            #pragma unroll
            for (int i = 0; i < 2; i++)
              #pragma unroll
              for (int j = 0; j < 8; j++)
                MMA_BF16(acc[i][j], afr[i], bfr[j]);
        }
        __syncthreads();
    }
    #pragma unroll
    for (int i = 0; i < 2; i++) {
        int row = bm0 + wm*32 + i*16 + g;
        #pragma unroll
        for (int j = 0; j < 8; j++) {
            int col = bn0 + wn*64 + j*8 + 2*tig;
            float b0 = 0.f, b1 = 0.f;
            if (MODE != 2) { b0 = bias[col]; b1 = bias[col+1]; }
            float v00 = acc[i][j][0] + b0, v01 = acc[i][j][1] + b1;
            float v10 = acc[i][j][2] + b0, v11 = acc[i][j][3] + b1;
            if (MODE == 2) {
                *(float2*)(&g_X[(size_t)row*DMODEL + col])     = make_float2(v00, v01);
                *(float2*)(&g_X[(size_t)(row+8)*DMODEL + col]) = make_float2(v10, v11);
            } else {
                __nv_bfloat16* o = (MODE == 1) ? g_Qbf : g_Kbf;
                *(__nv_bfloat162*)(&o[(size_t)row*DMODEL + col])     = __floats2bfloat162_rn(v00, v01);
                *(__nv_bfloat162*)(&o[(size_t)(row+8)*DMODEL + col]) = __floats2bfloat162_rn(v10, v11);
            }
        }
    }
}

// qw[b,n] = softmax over n of ||Qf[b,n,:]||
__global__ __launch_bounds__(64)
void qw_kernel()
{
    __shared__ float sv[NCAND], se[NCAND];
    const int b = blockIdx.x, t = threadIdx.x;
    const __nv_bfloat16* q = g_Qbf + (size_t)(b*NCAND + t)*DMODEL;
    float ssq = 0.f;
    #pragma unroll 8
    for (int d = 0; d < DMODEL; d += 2) {
        __nv_bfloat162 x = *(const __nv_bfloat162*)(q + d);
        float a = __low2float(x), c = __high2float(x);
        ssq += a*a + c*c;
    }
    float v = sqrtf(ssq);
    sv[t] = v;
    __syncthreads();
    float mx = -1e30f;
    for (int i = 0; i < NCAND; i++) mx = fmaxf(mx, sv[i]);
    float e = __expf(v - mx);
    se[t] = e;
    __syncthreads();
    float s = 0.f;
    for (int i = 0; i < NCAND; i++) s += se[i];
    g_qw[b*NCAND + t] = e / s;
}

// Per (b,h): scores via mma, row softmax, agg partial. grid (NHEADS, BATCH), 128 thr
#define QSTR 72
#define SSTR 204
#define ATTN_SMEM (64*QSTR*2 + HCLK*QSTR*2 + 64*SSTR*4)
__global__ __launch_bounds__(128)
void attn_kernel()
{
    extern __shared__ char sm[];
    __nv_bfloat16* Qs = (__nv_bfloat16*)sm;
    __nv_bfloat16* Ks = Qs + 64*QSTR;
    float* S = (float*)(sm + 64*QSTR*2 + HCLK*QSTR*2);
    __shared__ float coef[64], mrow[64];

    const int h = blockIdx.x, b = blockIdx.y;
    const int tid = threadIdx.x;
    const int warp = tid >> 5, lane = tid & 31;
    const int g = lane >> 2, tig = lane & 3;

    // load Q [64 x 64], K [200 x 64] head slices (uint4 = 8 bf16)
    for (int idx = tid; idx < 64*8; idx += 128) {
        int n = idx >> 3, c = (idx & 7) << 3;
        *(uint4*)(&Qs[n*QSTR + c]) =
            *(const uint4*)(g_Qbf + (size_t)(b*NCAND + n)*DMODEL + h*HDIM + c);
    }
    for (int idx = tid; idx < HCLK*8; idx += 128) {
        int m = idx >> 3, c = (idx & 7) << 3;
        *(uint4*)(&Ks[m*QSTR + c]) =
            *(const uint4*)(g_Kbf + (size_t)(b*HCLK + m)*DMODEL + h*HDIM + c);
    }
    __syncthreads();

    // scores: warp w -> rows [16w,16w+16), loop 25 col tiles of 8, K=64
    uint32_t afr[4][4];
    #pragma unroll
    for (int kt = 0; kt < 4; kt++) {
        const __nv_bfloat16* p = &Qs[(warp*16 + g)*QSTR + kt*16 + 2*tig];
        afr[kt][0] = *(const uint32_t*)(p);
        afr[kt][1] = *(const uint32_t*)(p + 8*QSTR);
        afr[kt][2] = *(const uint32_t*)(p + 8);
        afr[kt][3] = *(const uint32_t*)(p + 8*QSTR + 8);
    }
    const float iscale = rsqrtf((float)DMODEL);
    for (int nt = 0; nt < 25; nt++) {
        float c4[4] = {0.f, 0.f, 0.f, 0.f};
        #pragma unroll
        for (int kt = 0; kt < 4; kt++) {
            uint32_t bfr[2];
            const __nv_bfloat16* p = &Ks[(nt*8 + g)*QSTR + kt*16 + 2*tig];
            bfr[0] = *(const uint32_t*)(p);
            bfr[1] = *(const uint32_t*)(p + 8);
            MMA_BF16(c4, afr[kt], bfr);
        }
        int r0 = warp*16 + g, c0 = nt*8 + 2*tig;
        S[r0*SSTR + c0]     = c4[0] * iscale;
        S[r0*SSTR + c0+1]   = c4[1] * iscale;
        S[(r0+8)*SSTR + c0]   = c4[2] * iscale;
        S[(r0+8)*SSTR + c0+1] = c4[3] * iscale;
    }
    __syncthreads();

    // row softmax; coef[n] = qw[n]/den[n]; S <- exp(S-max)
    if (tid < 64) {
        float* r = &S[tid*SSTR];
        float mx = -1e30f;
        for (int m = 0; m < HCLK; m++) mx = fmaxf(mx, r[m]);
        float s = 0.f;
        for (int m = 0; m < HCLK; m++) { float e = __expf(r[m] - mx); r[m] = e; s += e; }
        coef[tid] = g_qw[b*NCAND + tid] / s;
        mrow[tid] = mx;
    }
    __syncthreads();

    // column reduce: aggp[b,h,m] = sum_n coef[n]*E[n][m]
    for (int m = tid; m < HCLK; m += 128) {
        float a = 0.f;
        #pragma unroll 8
        for (int n = 0; n < 64; n++) a += coef[n] * S[n*SSTR + m];
        g_aggp[((size_t)b*NHEADS + h)*HCLK + m] = a;
    }
}

// agg over heads + softmax -> aw; also write output tail. grid BATCH, 256 thr
__global__ __launch_bounds__(256)
void aggsm_kernel(float* __restrict__ out_tail)
{
    __shared__ float sa[HCLK], se2[HCLK];
    const int b = blockIdx.x, t = threadIdx.x;
    if (t < HCLK) {
        float a = 0.f;
        #pragma unroll
        for (int h = 0; h < NHEADS; h++)
            a += g_aggp[((size_t)b*NHEADS + h)*HCLK + t];
        sa[t] = a;
    }
    __syncthreads();
    if (t < HCLK) {
        float mx = -1e30f;
        for (int i = 0; i < HCLK; i++) mx = fmaxf(mx, sa[i]);
        se2[t] = __expf(sa[t] - mx);
    }
    __syncthreads();
    if (t < HCLK) {
        float s = 0.f;
        for (int i = 0; i < HCLK; i++) s += se2[i];
        float aw = se2[t] / s;
        g_aw[b*HCLK + t] = aw;
        out_tail[b*HCLK + t] = aw;
    }
}

// gate + residual + LayerNorm. grid MROWS_K, 128 thr
__global__ __launch_bounds__(128)
void epilogue_kernel(const float* __restrict__ clicked, const float* __restrict__ bg,
                     const float* __restrict__ gamma, const float* __restrict__ beta,
                     float* __restrict__ out)
{
    const int row = blockIdx.x, tid = threadIdx.x;
    const float aw = g_aw[row];
    const float* cp = clicked + (size_t)row*DMODEL;
    const float* xp = g_X + (size_t)row*DMODEL;
    float ov[5];
    float s = 0.f, sq = 0.f;
    #pragma unroll
    for (int i = 0; i < 5; i++) {
        int d = tid + i*128;
        float c = cp[d], x = xp[d];
        float z = aw * x + bg[d];
        float gate = 1.f / (1.f + __expf(-z));
        float wc = aw * c;
        float o = gate * wc + (1.f - gate) * c;
        ov[i] = o;
        s += o; sq += o*o;
    }
    // block reduce (4 warps)
    __shared__ float rs[4], rq[4];
    #pragma unroll
    for (int off = 16; off > 0; off >>= 1) {
        s  += __shfl_xor_sync(0xffffffffu, s, off);
        sq += __shfl_xor_sync(0xffffffffu, sq, off);
    }
    if ((tid & 31) == 0) { rs[tid >> 5] = s; rq[tid >> 5] = sq; }
    __syncthreads();
    float ts = rs[0] + rs[1] + rs[2] + rs[3];
    float tq = rq[0] + rq[1] + rq[2] + rq[3];
    float mu = ts / DMODEL;
    float var = tq / DMODEL - mu*mu;
    float inv = rsqrtf(var + 1e-5f);
    float* op = out + (size_t)row*DMODEL;
    #pragma unroll
    for (int i = 0; i < 5; i++) {
        int d = tid + i*128;
        op[d] = (ov[i] - mu) * inv * gamma[d] + beta[d];
    }
}

extern "C" void kernel_launch(void* const* d_in, const int* in_sizes, int n_in,
                              void* d_out, int out_size)
{
    const float* clicked_news   = (const float*)d_in[0];
    const float* clicked_topics = (const float*)d_in[1];
    const float* cand_topics    = (const float*)d_in[2];
    const float* Wq = (const float*)d_in[3];
    const float* bq = (const float*)d_in[4];
    const float* Wk = (const float*)d_in[5];
    const float* bk = (const float*)d_in[6];
    const float* Wg = (const float*)d_in[9];
    const float* bg = (const float*)d_in[10];
    const float* ln_gamma = (const float*)d_in[11];
    const float* ln_beta  = (const float*)d_in[12];
    float* out = (float*)d_out;

    cudaFuncSetAttribute(attn_kernel, cudaFuncAttributeMaxDynamicSharedMemorySize, ATTN_SMEM);

    gemm_kernel<0><<<dim3(5, MROWS_K/128), 256>>>(clicked_topics, Wk, bk, MROWS_K, 256);
    gemm_kernel<1><<<dim3(5, MROWS_Q/128), 256>>>(cand_topics,    Wq, bq, MROWS_Q, 256);
    gemm_kernel<2><<<dim3(5, MROWS_K/128), 256>>>(clicked_news,   Wg, bg, MROWS_K, DMODEL);
    qw_kernel<<<BATCH, 64>>>();
    attn_kernel<<<dim3(NHEADS, BATCH), 128, ATTN_SMEM>>>();
    aggsm_kernel<<<BATCH, 256>>>(out + (size_t)MROWS_K*DMODEL);
    epilogue_kernel<<<MROWS_K, 128>>>(clicked_news, bg, ln_gamma, ln_beta, out);
}

// round 4
// speedup vs baseline: 1.0146x; 1.0146x over previous
#include <cuda_runtime.h>
#include <cuda_bf16.h>
#include <cstdint>
#include <cstddef>
#include <math.h>

#define BATCH  256
#define HCLK   200
#define NCAND  64
#define DMODEL 640
#define NHEADS 10
#define HDIM   64
#define MROWS_K (BATCH*HCLK)
#define MROWS_Q (BATCH*NCAND)

// ---- scratch ----
__device__ __nv_bfloat16 g_Anb[(size_t)MROWS_K*DMODEL];   // clicked_news bf16
__device__ __nv_bfloat16 g_Atb[(size_t)MROWS_K*256];      // clicked_topics bf16
__device__ __nv_bfloat16 g_Acb[(size_t)MROWS_Q*256];      // cand_topics bf16
__device__ __nv_bfloat16 g_Wkb[DMODEL*256];
__device__ __nv_bfloat16 g_Wqb[DMODEL*256];
__device__ __nv_bfloat16 g_Wgb[DMODEL*DMODEL];
__device__ __nv_bfloat16 g_Qbf[(size_t)MROWS_Q*DMODEL];
__device__ __nv_bfloat16 g_Kbf[(size_t)MROWS_K*DMODEL];
__device__ __nv_bfloat16 g_X  [(size_t)MROWS_K*DMODEL];
__device__ float         g_qw [MROWS_Q];
__device__ float         g_aggp[(size_t)BATCH*NHEADS*HCLK];
__device__ float         g_aw [MROWS_K];

#define MMA_BF16(d, a, b) \
  asm volatile( \
    "mma.sync.aligned.m16n8k16.row.col.f32.bf16.bf16.f32 " \
    "{%0,%1,%2,%3}, {%4,%5,%6,%7}, {%8,%9}, {%0,%1,%2,%3};\n" \
    : "+f"((d)[0]), "+f"((d)[1]), "+f"((d)[2]), "+f"((d)[3]) \
    : "r"((a)[0]), "r"((a)[1]), "r"((a)[2]), "r"((a)[3]), \
      "r"((b)[0]), "r"((b)[1]))

#define CP16(dst, src) do { \
    uint32_t _d = (uint32_t)__cvta_generic_to_shared(dst); \
    asm volatile("cp.async.cg.shared.global [%0], [%1], 16;\n" :: "r"(_d), "l"(src)); \
  } while (0)

// ---- fp32 -> bf16 convert ----
__global__ __launch_bounds__(256)
void f2bf_kernel(const float* __restrict__ in, __nv_bfloat16* __restrict__ out, int n)
{
    int i = (blockIdx.x*256 + threadIdx.x)*4;
    if (i < n) {
        float4 v = *(const float4*)(in + i);
        *(__nv_bfloat162*)(out + i)     = __floats2bfloat162_rn(v.x, v.y);
        *(__nv_bfloat162*)(out + i + 2) = __floats2bfloat162_rn(v.z, v.w);
    }
}

// ---- bf16 GEMM: C[M,640] = A[M,K] @ W[640,K]^T (+bias), cp.async double-buffered ----
#define SST 72
#define GEMM_SMEM (2*256*SST*2)   // 2 stages * (As 128*72 + Bs 128*72) bf16
template<bool BIAS>
__global__ __launch_bounds__(256)
void gemm_bf16(const __nv_bfloat16* __restrict__ A, const __nv_bfloat16* __restrict__ W,
               const float* __restrict__ bias, __nv_bfloat16* __restrict__ C, int K)
{
    extern __shared__ __nv_bfloat16 sh[];
    const int tid = threadIdx.x;
    const int bn0 = blockIdx.x*128, bm0 = blockIdx.y*128;
    const int warp = tid >> 5, lane = tid & 31;
    const int wm = warp & 3, wn = warp >> 2;
    const int g = lane >> 2, tig = lane & 3;

    float acc[2][8][4];
    #pragma unroll
    for (int i = 0; i < 2; i++)
      #pragma unroll
      for (int j = 0; j < 8; j++)
        #pragma unroll
        for (int v = 0; v < 4; v++) acc[i][j][v] = 0.f;

    const int nk = K / 64;

    auto issue = [&](int kb, int s) {
        const int k0 = kb * 64;
        __nv_bfloat16* As = sh + s*(256*SST);
        __nv_bfloat16* Bs = As + 128*SST;
        #pragma unroll
        for (int it = 0; it < 4; it++) {
            int idx = tid + it*256;           // 0..1023
            int r = idx >> 3, c8 = (idx & 7) << 3;
            CP16(&As[r*SST + c8], &A[(size_t)(bm0 + r)*K + k0 + c8]);
            CP16(&Bs[r*SST + c8], &W[(size_t)(bn0 + r)*K + k0 + c8]);
        }
        asm volatile("cp.async.commit_group;\n");
    };

    issue(0, 0);
    for (int kb = 0; kb < nk; kb++) {
        if (kb + 1 < nk) {
            issue(kb + 1, (kb + 1) & 1);
            asm volatile("cp.async.wait_group 1;\n");
        } else {
            asm volatile("cp.async.wait_group 0;\n");
        }
        __syncthreads();
        const __nv_bfloat16* As = sh + (kb & 1)*(256*SST);
        const __nv_bfloat16* Bs = As + 128*SST;
        #pragma unroll
        for (int ks = 0; ks < 4; ks++) {
            const int kk = ks*16 + 2*tig;
            uint32_t afr[2][4];
            #pragma unroll
            for (int i = 0; i < 2; i++) {
                const __nv_bfloat16* p = &As[(wm*32 + i*16 + g)*SST + kk];
                afr[i][0] = *(const uint32_t*)(p);
                afr[i][1] = *(const uint32_t*)(p + 8*SST);
                afr[i][2] = *(const uint32_t*)(p + 8);
                afr[i][3] = *(const uint32_t*)(p + 8*SST + 8);
            }
            uint32_t bfr[8][2];
            #pragma unroll
            for (int j = 0; j < 8; j++) {
                const __nv_bfloat16* p = &Bs[(wn*64 + j*8 + g)*SST + kk];
                bfr[j][0] = *(const uint32_t*)(p);
                bfr[j][1] = *(const uint32_t*)(p + 8);
            }
            #pragma unroll
            for (int i = 0; i < 2; i++)
              #pragma unroll
              for (int j = 0; j < 8; j++)
                MMA_BF16(acc[i][j], afr[i], bfr[j]);
        }
        __syncthreads();
    }

    #pragma unroll
    for (int i = 0; i < 2; i++) {
        int row = bm0 + wm*32 + i*16 + g;
        #pragma unroll
        for (int j = 0; j < 8; j++) {
            int col = bn0 + wn*64 + j*8 + 2*tig;
            float b0 = 0.f, b1 = 0.f;
            if (BIAS) { b0 = bias[col]; b1 = bias[col+1]; }
            *(__nv_bfloat162*)(&C[(size_t)row*DMODEL + col]) =
                __floats2bfloat162_rn(acc[i][j][0] + b0, acc[i][j][1] + b1);
            *(__nv_bfloat162*)(&C[(size_t)(row+8)*DMODEL + col]) =
                __floats2bfloat162_rn(acc[i][j][2] + b0, acc[i][j][3] + b1);
        }
    }
}

// ---- qw[b,n] = softmax over n of ||Qf[b,n,:]|| ----
__global__ __launch_bounds__(256)
void qw_kernel()
{
    __shared__ float sv[NCAND], se[NCAND];
    const int b = blockIdx.x, tid = threadIdx.x;
    const int warp = tid >> 5, lane = tid & 31;
    for (int n = warp; n < NCAND; n += 8) {
        const __nv_bfloat16* q = g_Qbf + (size_t)(b*NCAND + n)*DMODEL;
        float ssq = 0.f;
        #pragma unroll
        for (int i = 0; i < 5; i++) {
            int c = (lane + i*32)*4;
            __nv_bfloat162 x0 = *(const __nv_bfloat162*)(q + c);
            __nv_bfloat162 x1 = *(const __nv_bfloat162*)(q + c + 2);
            float a = __low2float(x0), d = __high2float(x0);
            float e = __low2float(x1), f = __high2float(x1);
            ssq += a*a + d*d + e*e + f*f;
        }
        #pragma unroll
        for (int o = 16; o; o >>= 1) ssq += __shfl_xor_sync(0xffffffffu, ssq, o);
        if (lane == 0) sv[n] = sqrtf(ssq);
    }
    __syncthreads();
    if (tid < NCAND) {
        float mx = -1e30f;
        for (int i = 0; i < NCAND; i++) mx = fmaxf(mx, sv[i]);
        se[tid] = __expf(sv[tid] - mx);
    }
    __syncthreads();
    if (tid < NCAND) {
        float s = 0.f;
        for (int i = 0; i < NCAND; i++) s += se[i];
        g_qw[b*NCAND + tid] = se[tid] / s;
    }
}

// ---- attention per (b,h): scores -> softmax -> weighted column reduce ----
#define QSTR 72
#define SSTR 204
#define ATTN_SMEM ((64*QSTR + HCLK*QSTR)*2 + 64*SSTR*4)
__global__ __launch_bounds__(128)
void attn_kernel()
{
    extern __shared__ char sm[];
    __nv_bfloat16* Qs = (__nv_bfloat16*)sm;
    __nv_bfloat16* Ks = Qs + 64*QSTR;
    float* S = (float*)(sm + (64*QSTR + HCLK*QSTR)*2);
    __shared__ float coef[64];

    const int h = blockIdx.x, b = blockIdx.y;
    const int tid = threadIdx.x;
    const int warp = tid >> 5, lane = tid & 31;
    const int g = lane >> 2, tig = lane & 3;

    for (int idx = tid; idx < 64*8; idx += 128) {
        int n = idx >> 3, c = (idx & 7) << 3;
        *(uint4*)(&Qs[n*QSTR + c]) =
            *(const uint4*)(g_Qbf + (size_t)(b*NCAND + n)*DMODEL + h*HDIM + c);
    }
    for (int idx = tid; idx < HCLK*8; idx += 128) {
        int m = idx >> 3, c = (idx & 7) << 3;
        *(uint4*)(&Ks[m*QSTR + c]) =
            *(const uint4*)(g_Kbf + (size_t)(b*HCLK + m)*DMODEL + h*HDIM + c);
    }
    __syncthreads();

    uint32_t afr[4][4];
    #pragma unroll
    for (int kt = 0; kt < 4; kt++) {
        const __nv_bfloat16* p = &Qs[(warp*16 + g)*QSTR + kt*16 + 2*tig];
        afr[kt][0] = *(const uint32_t*)(p);
        afr[kt][1] = *(const uint32_t*)(p + 8*QSTR);
        afr[kt][2] = *(const uint32_t*)(p + 8);
        afr[kt][3] = *(const uint32_t*)(p + 8*QSTR + 8);
    }
    const float iscale = rsqrtf((float)DMODEL);
    for (int nt = 0; nt < 25; nt++) {
        float c4[4] = {0.f, 0.f, 0.f, 0.f};
        #pragma unroll
        for (int kt = 0; kt < 4; kt++) {
            uint32_t bfr[2];
            const __nv_bfloat16* p = &Ks[(nt*8 + g)*QSTR + kt*16 + 2*tig];
            bfr[0] = *(const uint32_t*)(p);
            bfr[1] = *(const uint32_t*)(p + 8);
            MMA_BF16(c4, afr[kt], bfr);
        }
        int r0 = warp*16 + g, c0 = nt*8 + 2*tig;
        S[r0*SSTR + c0]       = c4[0] * iscale;
        S[r0*SSTR + c0+1]     = c4[1] * iscale;
        S[(r0+8)*SSTR + c0]   = c4[2] * iscale;
        S[(r0+8)*SSTR + c0+1] = c4[3] * iscale;
    }
    __syncthreads();

    // warp-per-row softmax; coef[n] = qw[n] / den[n]
    for (int n = warp; n < 64; n += 4) {
        float mx = -1e30f;
        for (int m = lane; m < HCLK; m += 32) mx = fmaxf(mx, S[n*SSTR + m]);
        #pragma unroll
        for (int o = 16; o; o >>= 1) mx = fmaxf(mx, __shfl_xor_sync(0xffffffffu, mx, o));
        float s = 0.f;
        for (int m = lane; m < HCLK; m += 32) {
            float e = __expf(S[n*SSTR + m] - mx);
            S[n*SSTR + m] = e;
            s += e;
        }
        #pragma unroll
        for (int o = 16; o; o >>= 1) s += __shfl_xor_sync(0xffffffffu, s, o);
        if (lane == 0) coef[n] = g_qw[b*NCAND + n] / s;
    }
    __syncthreads();

    for (int m = tid; m < HCLK; m += 128) {
        float a = 0.f;
        #pragma unroll 8
        for (int n = 0; n < 64; n++) a += coef[n] * S[n*SSTR + m];
        g_aggp[((size_t)b*NHEADS + h)*HCLK + m] = a;
    }
}

// ---- head-reduce + softmax -> aw ----
__global__ __launch_bounds__(256)
void aggsm_kernel(float* __restrict__ out_tail)
{
    __shared__ float sa[HCLK], se2[HCLK];
    const int b = blockIdx.x, t = threadIdx.x;
    if (t < HCLK) {
        float a = 0.f;
        #pragma unroll
        for (int h = 0; h < NHEADS; h++)
            a += g_aggp[((size_t)b*NHEADS + h)*HCLK + t];
        sa[t] = a;
    }
    __syncthreads();
    if (t < HCLK) {
        float mx = -1e30f;
        for (int i = 0; i < HCLK; i++) mx = fmaxf(mx, sa[i]);
        se2[t] = __expf(sa[t] - mx);
    }
    __syncthreads();
    if (t < HCLK) {
        float s = 0.f;
        for (int i = 0; i < HCLK; i++) s += se2[i];
        float aw = se2[t] / s;
        g_aw[b*HCLK + t] = aw;
        out_tail[b*HCLK + t] = aw;
    }
}

// ---- gate + residual + LayerNorm ----
__global__ __launch_bounds__(128)
void epilogue_kernel(const float* __restrict__ clicked, const float* __restrict__ bg,
                     const float* __restrict__ gamma, const float* __restrict__ beta,
                     float* __restrict__ out)
{
    const int row = blockIdx.x, tid = threadIdx.x;
    const float aw = g_aw[row];
    const float* cp = clicked + (size_t)row*DMODEL;
    const __nv_bfloat16* xp = g_X + (size_t)row*DMODEL;
    float ov[5];
    float s = 0.f, sq = 0.f;
    #pragma unroll
    for (int i = 0; i < 5; i++) {
        int d = tid + i*128;
        float c = cp[d];
        float x = __bfloat162float(xp[d]);
        float z = aw * x + bg[d];
        float gate = 1.f / (1.f + __expf(-z));
        float o = gate * (aw * c) + (1.f - gate) * c;
        ov[i] = o;
        s += o; sq += o*o;
    }
    __shared__ float rs[4], rq[4];
    #pragma unroll
    for (int off = 16; off > 0; off >>= 1) {
        s  += __shfl_xor_sync(0xffffffffu, s, off);
        sq += __shfl_xor_sync(0xffffffffu, sq, off);
    }
    if ((tid & 31) == 0) { rs[tid >> 5] = s; rq[tid >> 5] = sq; }
    __syncthreads();
    float ts = rs[0] + rs[1] + rs[2] + rs[3];
    float tq = rq[0] + rq[1] + rq[2] + rq[3];
    float mu = ts / DMODEL;
    float var = tq / DMODEL - mu*mu;
    float inv = rsqrtf(var + 1e-5f);
    float* op = out + (size_t)row*DMODEL;
    #pragma unroll
    for (int i = 0; i < 5; i++) {
        int d = tid + i*128;
        op[d] = (ov[i] - mu) * inv * gamma[d] + beta[d];
    }
}

extern "C" void kernel_launch(void* const* d_in, const int* in_sizes, int n_in,
                              void* d_out, int out_size)
{
    const float* clicked_news   = (const float*)d_in[0];
    const float* clicked_topics = (const float*)d_in[1];
    const float* cand_topics    = (const float*)d_in[2];
    const float* Wq = (const float*)d_in[3];
    const float* bq = (const float*)d_in[4];
    const float* Wk = (const float*)d_in[5];
    const float* bk = (const float*)d_in[6];
    const float* Wg = (const float*)d_in[9];
    const float* bg = (const float*)d_in[10];
    const float* ln_gamma = (const float*)d_in[11];
    const float* ln_beta  = (const float*)d_in[12];
    float* out = (float*)d_out;

    cudaFuncSetAttribute(gemm_bf16<true>,  cudaFuncAttributeMaxDynamicSharedMemorySize, GEMM_SMEM);
    cudaFuncSetAttribute(gemm_bf16<false>, cudaFuncAttributeMaxDynamicSharedMemorySize, GEMM_SMEM);
    cudaFuncSetAttribute(attn_kernel, cudaFuncAttributeMaxDynamicSharedMemorySize, ATTN_SMEM);

    __nv_bfloat16 *p_Anb, *p_Atb, *p_Acb, *p_Wkb, *p_Wqb, *p_Wgb;
    cudaGetSymbolAddress((void**)&p_Anb, g_Anb);
    cudaGetSymbolAddress((void**)&p_Atb, g_Atb);
    cudaGetSymbolAddress((void**)&p_Acb, g_Acb);
    cudaGetSymbolAddress((void**)&p_Wkb, g_Wkb);
    cudaGetSymbolAddress((void**)&p_Wqb, g_Wqb);
    cudaGetSymbolAddress((void**)&p_Wgb, g_Wgb);
    __nv_bfloat16 *p_Qbf, *p_Kbf, *p_X;
    cudaGetSymbolAddress((void**)&p_Qbf, g_Qbf);
    cudaGetSymbolAddress((void**)&p_Kbf, g_Kbf);
    cudaGetSymbolAddress((void**)&p_X,   g_X);

    f2bf_kernel<<<32000, 256>>>(clicked_news,   p_Anb, MROWS_K*DMODEL);
    f2bf_kernel<<<12800, 256>>>(clicked_topics, p_Atb, MROWS_K*256);
    f2bf_kernel<<<4096,  256>>>(cand_topics,    p_Acb, MROWS_Q*256);
    f2bf_kernel<<<160,   256>>>(Wk, p_Wkb, DMODEL*256);
    f2bf_kernel<<<160,   256>>>(Wq, p_Wqb, DMODEL*256);
    f2bf_kernel<<<400,   256>>>(Wg, p_Wgb, DMODEL*DMODEL);

    gemm_bf16<true><<<dim3(5, MROWS_K/128), 256, GEMM_SMEM>>>(p_Atb, p_Wkb, bk, p_Kbf, 256);
    gemm_bf16<true><<<dim3(5, MROWS_Q/128), 256, GEMM_SMEM>>>(p_Acb, p_Wqb, bq, p_Qbf, 256);
    gemm_bf16<false><<<dim3(5, MROWS_K/128), 256, GEMM_SMEM>>>(p_Anb, p_Wgb, nullptr, p_X, DMODEL);

    qw_kernel<<<BATCH, 256>>>();
    attn_kernel<<<dim3(NHEADS, BATCH), 128, ATTN_SMEM>>>();
    aggsm_kernel<<<BATCH, 256>>>(out + (size_t)MROWS_K*DMODEL);
    epilogue_kernel<<<MROWS_K, 128>>>(clicked_news, bg, ln_gamma, ln_beta, out);
}

// round 7
// speedup vs baseline: 1.1234x; 1.1072x over previous
#include <cuda_runtime.h>
#include <cuda_bf16.h>
#include <cstdint>
#include <cstddef>
#include <math.h>

#define BATCH  256
#define HCLK   200
#define NCAND  64
#define DMODEL 640
#define NHEADS 10
#define HDIM   64
#define MROWS_K (BATCH*HCLK)
#define MROWS_Q (BATCH*NCAND)

// ---- scratch ----
__device__ __nv_bfloat16 g_Anb[(size_t)MROWS_K*DMODEL];
__device__ __nv_bfloat16 g_Atb[(size_t)MROWS_K*256];
__device__ __nv_bfloat16 g_Acb[(size_t)MROWS_Q*256];
__device__ __nv_bfloat16 g_Wkb[DMODEL*256];
__device__ __nv_bfloat16 g_Wqb[DMODEL*256];
__device__ __nv_bfloat16 g_Wgb[DMODEL*DMODEL];
__device__ __nv_bfloat16 g_Qbf[(size_t)MROWS_Q*DMODEL];
__device__ __nv_bfloat16 g_Kbf[(size_t)MROWS_K*DMODEL];
__device__ __nv_bfloat16 g_X  [(size_t)MROWS_K*DMODEL];
__device__ float         g_qw [MROWS_Q];
__device__ float         g_aggp[(size_t)BATCH*NHEADS*HCLK];
__device__ float         g_aw [MROWS_K];

#define MMA_BF16(d, a, b) \
  asm volatile( \
    "mma.sync.aligned.m16n8k16.row.col.f32.bf16.bf16.f32 " \
    "{%0,%1,%2,%3}, {%4,%5,%6,%7}, {%8,%9}, {%0,%1,%2,%3};\n" \
    : "+f"((d)[0]), "+f"((d)[1]), "+f"((d)[2]), "+f"((d)[3]) \
    : "r"((a)[0]), "r"((a)[1]), "r"((a)[2]), "r"((a)[3]), \
      "r"((b)[0]), "r"((b)[1]))

#define LDSM_X4(r0, r1, r2, r3, saddr) \
  asm volatile("ldmatrix.sync.aligned.m8n8.x4.shared.b16 {%0,%1,%2,%3}, [%4];\n" \
    : "=r"(r0), "=r"(r1), "=r"(r2), "=r"(r3) : "r"(saddr))

#define CP16(dst, src) do { \
    uint32_t _d = (uint32_t)__cvta_generic_to_shared(dst); \
    asm volatile("cp.async.cg.shared.global [%0], [%1], 16;\n" :: "r"(_d), "l"(src)); \
  } while (0)

// ---- fp32 -> bf16 converts ----
__global__ __launch_bounds__(256)
void f2bf_kernel(const float* __restrict__ in, __nv_bfloat16* __restrict__ out, int n)
{
    int i = (blockIdx.x*256 + threadIdx.x)*4;
    if (i < n) {
        float4 v = *(const float4*)(in + i);
        *(__nv_bfloat162*)(out + i)     = __floats2bfloat162_rn(v.x, v.y);
        *(__nv_bfloat162*)(out + i + 2) = __floats2bfloat162_rn(v.z, v.w);
    }
}
__global__ __launch_bounds__(256)
void f2bfw_kernel(const float* __restrict__ a, __nv_bfloat16* __restrict__ oa, int na,
                  const float* __restrict__ b, __nv_bfloat16* __restrict__ ob, int nb,
                  const float* __restrict__ c, __nv_bfloat16* __restrict__ oc, int nc)
{
    int stride = gridDim.x*256*4;
    for (int i = (blockIdx.x*256 + threadIdx.x)*4; i < na; i += stride) {
        float4 v = *(const float4*)(a + i);
        *(__nv_bfloat162*)(oa + i)     = __floats2bfloat162_rn(v.x, v.y);
        *(__nv_bfloat162*)(oa + i + 2) = __floats2bfloat162_rn(v.z, v.w);
    }
    for (int i = (blockIdx.x*256 + threadIdx.x)*4; i < nb; i += stride) {
        float4 v = *(const float4*)(b + i);
        *(__nv_bfloat162*)(ob + i)     = __floats2bfloat162_rn(v.x, v.y);
        *(__nv_bfloat162*)(ob + i + 2) = __floats2bfloat162_rn(v.z, v.w);
    }
    for (int i = (blockIdx.x*256 + threadIdx.x)*4; i < nc; i += stride) {
        float4 v = *(const float4*)(c + i);
        *(__nv_bfloat162*)(oc + i)     = __floats2bfloat162_rn(v.x, v.y);
        *(__nv_bfloat162*)(oc + i + 2) = __floats2bfloat162_rn(v.z, v.w);
    }
}

// ---- bf16 GEMM: C[M,640] = A[M,K] @ W[640,K]^T (+bias), cp.async 2-stage, ldmatrix ----
#define SST 72
#define GEMM_SMEM (2*256*SST*2)
template<bool BIAS>
__global__ __launch_bounds__(256)
void gemm_bf16(const __nv_bfloat16* __restrict__ A, const __nv_bfloat16* __restrict__ W,
               const float* __restrict__ bias, __nv_bfloat16* __restrict__ C, int K)
{
    extern __shared__ __nv_bfloat16 sh[];
    const int tid = threadIdx.x;
    const int bn0 = blockIdx.x*128, bm0 = blockIdx.y*128;
    const int warp = tid >> 5, lane = tid & 31;
    const int wm = warp & 3, wn = warp >> 2;
    const int g = lane >> 2, tig = lane & 3;

    // ldmatrix per-lane row/col selectors
    const int a_r = lane & 15;            // row within 16-row A tile
    const int a_c = (lane >> 4) << 3;     // 0 or 8 (k offset)
    const int b_r = ((lane >> 4) << 3) + (lane & 7);  // row within 16-row B pair
    const int b_c = ((lane >> 3) & 1) << 3;           // 0 or 8 (k offset)

    float acc[2][8][4];
    #pragma unroll
    for (int i = 0; i < 2; i++)
      #pragma unroll
      for (int j = 0; j < 8; j++)
        #pragma unroll
        for (int v = 0; v < 4; v++) acc[i][j][v] = 0.f;

    const int nk = K / 64;

    auto issue = [&](int kb, int s) {
        const int k0 = kb * 64;
        __nv_bfloat16* As = sh + s*(256*SST);
        __nv_bfloat16* Bs = As + 128*SST;
        #pragma unroll
        for (int it = 0; it < 4; it++) {
            int idx = tid + it*256;
            int r = idx >> 3, c8 = (idx & 7) << 3;
            CP16(&As[r*SST + c8], &A[(size_t)(bm0 + r)*K + k0 + c8]);
            CP16(&Bs[r*SST + c8], &W[(size_t)(bn0 + r)*K + k0 + c8]);
        }
        asm volatile("cp.async.commit_group;\n");
    };

    issue(0, 0);
    for (int kb = 0; kb < nk; kb++) {
        if (kb + 1 < nk) {
            issue(kb + 1, (kb + 1) & 1);
            asm volatile("cp.async.wait_group 1;\n");
        } else {
            asm volatile("cp.async.wait_group 0;\n");
        }
        __syncthreads();
        const __nv_bfloat16* As = sh + (kb & 1)*(256*SST);
        const __nv_bfloat16* Bs = As + 128*SST;
        uint32_t As0 = (uint32_t)__cvta_generic_to_shared(As);
        uint32_t Bs0 = (uint32_t)__cvta_generic_to_shared(Bs);
        #pragma unroll
        for (int ks = 0; ks < 4; ks++) {
            const int kk = ks*16;
            uint32_t afr[2][4];
            #pragma unroll
            for (int i = 0; i < 2; i++) {
                uint32_t ad = As0 + ((wm*32 + i*16 + a_r)*SST + kk + a_c)*2;
                LDSM_X4(afr[i][0], afr[i][1], afr[i][2], afr[i][3], ad);
            }
            uint32_t bfr[4][4];
            #pragma unroll
            for (int j2 = 0; j2 < 4; j2++) {
                uint32_t bd = Bs0 + ((wn*64 + j2*16 + b_r)*SST + kk + b_c)*2;
                LDSM_X4(bfr[j2][0], bfr[j2][1], bfr[j2][2], bfr[j2][3], bd);
            }
            #pragma unroll
            for (int i = 0; i < 2; i++)
              #pragma unroll
              for (int j2 = 0; j2 < 4; j2++) {
                MMA_BF16(acc[i][2*j2],   afr[i], (&bfr[j2][0]));
                MMA_BF16(acc[i][2*j2+1], afr[i], (&bfr[j2][2]));
              }
        }
        __syncthreads();
    }

    #pragma unroll
    for (int i = 0; i < 2; i++) {
        int row = bm0 + wm*32 + i*16 + g;
        #pragma unroll
        for (int j = 0; j < 8; j++) {
            int col = bn0 + wn*64 + j*8 + 2*tig;
            float b0 = 0.f, b1 = 0.f;
            if (BIAS) { b0 = bias[col]; b1 = bias[col+1]; }
            *(__nv_bfloat162*)(&C[(size_t)row*DMODEL + col]) =
                __floats2bfloat162_rn(acc[i][j][0] + b0, acc[i][j][1] + b1);
            *(__nv_bfloat162*)(&C[(size_t)(row+8)*DMODEL + col]) =
                __floats2bfloat162_rn(acc[i][j][2] + b0, acc[i][j][3] + b1);
        }
    }
}

// ---- qw ----
__global__ __launch_bounds__(256)
void qw_kernel()
{
    __shared__ float sv[NCAND], se[NCAND];
    const int b = blockIdx.x, tid = threadIdx.x;
    const int warp = tid >> 5, lane = tid & 31;
    for (int n = warp; n < NCAND; n += 8) {
        const __nv_bfloat16* q = g_Qbf + (size_t)(b*NCAND + n)*DMODEL;
        float ssq = 0.f;
        #pragma unroll
        for (int i = 0; i < 5; i++) {
            int c = (lane + i*32)*4;
            __nv_bfloat162 x0 = *(const __nv_bfloat162*)(q + c);
            __nv_bfloat162 x1 = *(const __nv_bfloat162*)(q + c + 2);
            float a = __low2float(x0), d = __high2float(x0);
            float e = __low2float(x1), f = __high2float(x1);
            ssq += a*a + d*d + e*e + f*f;
        }
        #pragma unroll
        for (int o = 16; o; o >>= 1) ssq += __shfl_xor_sync(0xffffffffu, ssq, o);
        if (lane == 0) sv[n] = sqrtf(ssq);
    }
    __syncthreads();
    if (tid < NCAND) {
        float mx = -1e30f;
        for (int i = 0; i < NCAND; i++) mx = fmaxf(mx, sv[i]);
        se[tid] = __expf(sv[tid] - mx);
    }
    __syncthreads();
    if (tid < NCAND) {
        float s = 0.f;
        for (int i = 0; i < NCAND; i++) s += se[i];
        g_qw[b*NCAND + tid] = se[tid] / s;
    }
}

// ---- attention per (b,h) ----
#define QSTR 72
#define SSTR 204
#define ATTN_SMEM ((64*QSTR + HCLK*QSTR)*2 + 64*SSTR*4)
__global__ __launch_bounds__(128)
void attn_kernel()
{
    extern __shared__ char sm[];
    __nv_bfloat16* Qs = (__nv_bfloat16*)sm;
    __nv_bfloat16* Ks = Qs + 64*QSTR;
    float* S = (float*)(sm + (64*QSTR + HCLK*QSTR)*2);
    __shared__ float coef[64];

    const int h = blockIdx.x, b = blockIdx.y;
    const int tid = threadIdx.x;
    const int warp = tid >> 5, lane = tid & 31;
    const int g = lane >> 2, tig = lane & 3;

    for (int idx = tid; idx < 64*8; idx += 128) {
        int n = idx >> 3, c = (idx & 7) << 3;
        *(uint4*)(&Qs[n*QSTR + c]) =
            *(const uint4*)(g_Qbf + (size_t)(b*NCAND + n)*DMODEL + h*HDIM + c);
    }
    for (int idx = tid; idx < HCLK*8; idx += 128) {
        int m = idx >> 3, c = (idx & 7) << 3;
        *(uint4*)(&Ks[m*QSTR + c]) =
            *(const uint4*)(g_Kbf + (size_t)(b*HCLK + m)*DMODEL + h*HDIM + c);
    }
    __syncthreads();

    uint32_t afr[4][4];
    #pragma unroll
    for (int kt = 0; kt < 4; kt++) {
        const __nv_bfloat16* p = &Qs[(warp*16 + g)*QSTR + kt*16 + 2*tig];
        afr[kt][0] = *(const uint32_t*)(p);
        afr[kt][1] = *(const uint32_t*)(p + 8*QSTR);
        afr[kt][2] = *(const uint32_t*)(p + 8);
        afr[kt][3] = *(const uint32_t*)(p + 8*QSTR + 8);
    }
    const float iscale = rsqrtf((float)DMODEL);
    for (int nt = 0; nt < 25; nt++) {
        float c4[4] = {0.f, 0.f, 0.f, 0.f};
        #pragma unroll
        for (int kt = 0; kt < 4; kt++) {
            uint32_t bfr[2];
            const __nv_bfloat16* p = &Ks[(nt*8 + g)*QSTR + kt*16 + 2*tig];
            bfr[0] = *(const uint32_t*)(p);
            bfr[1] = *(const uint32_t*)(p + 8);
            MMA_BF16(c4, afr[kt], bfr);
        }
        int r0 = warp*16 + g, c0 = nt*8 + 2*tig;
        S[r0*SSTR + c0]       = c4[0] * iscale;
        S[r0*SSTR + c0+1]     = c4[1] * iscale;
        S[(r0+8)*SSTR + c0]   = c4[2] * iscale;
        S[(r0+8)*SSTR + c0+1] = c4[3] * iscale;
    }
    __syncthreads();

    for (int n = warp; n < 64; n += 4) {
        float mx = -1e30f;
        for (int m = lane; m < HCLK; m += 32) mx = fmaxf(mx, S[n*SSTR + m]);
        #pragma unroll
        for (int o = 16; o; o >>= 1) mx = fmaxf(mx, __shfl_xor_sync(0xffffffffu, mx, o));
        float s = 0.f;
        for (int m = lane; m < HCLK; m += 32) {
            float e = __expf(S[n*SSTR + m] - mx);
            S[n*SSTR + m] = e;
            s += e;
        }
        #pragma unroll
        for (int o = 16; o; o >>= 1) s += __shfl_xor_sync(0xffffffffu, s, o);
        if (lane == 0) coef[n] = g_qw[b*NCAND + n] / s;
    }
    __syncthreads();

    for (int m = tid; m < HCLK; m += 128) {
        float a = 0.f;
        #pragma unroll 8
        for (int n = 0; n < 64; n++) a += coef[n] * S[n*SSTR + m];
        g_aggp[((size_t)b*NHEADS + h)*HCLK + m] = a;
    }
}

// ---- head-reduce + softmax -> aw ----
__global__ __launch_bounds__(256)
void aggsm_kernel(float* __restrict__ out_tail)
{
    __shared__ float sa[HCLK], se2[HCLK];
    const int b = blockIdx.x, t = threadIdx.x;
    if (t < HCLK) {
        float a = 0.f;
        #pragma unroll
        for (int h = 0; h < NHEADS; h++)
            a += g_aggp[((size_t)b*NHEADS + h)*HCLK + t];
        sa[t] = a;
    }
    __syncthreads();
    if (t < HCLK) {
        float mx = -1e30f;
        for (int i = 0; i < HCLK; i++) mx = fmaxf(mx, sa[i]);
        se2[t] = __expf(sa[t] - mx);
    }
    __syncthreads();
    if (t < HCLK) {
        float s = 0.f;
        for (int i = 0; i < HCLK; i++) s += se2[i];
        float aw = se2[t] / s;
        g_aw[b*HCLK + t] = aw;
        out_tail[b*HCLK + t] = aw;
    }
}

// ---- gate + residual + LayerNorm ----
__global__ __launch_bounds__(128)
void epilogue_kernel(const float* __restrict__ clicked, const float* __restrict__ bg,
                     const float* __restrict__ gamma, const float* __restrict__ beta,
                     float* __restrict__ out)
{
    const int row = blockIdx.x, tid = threadIdx.x;
    const float aw = g_aw[row];
    const float* cp = clicked + (size_t)row*DMODEL;
    const __nv_bfloat16* xp = g_X + (size_t)row*DMODEL;
    float ov[5];
    float s = 0.f, sq = 0.f;
    #pragma unroll
    for (int i = 0; i < 5; i++) {
        int d = tid + i*128;
        float c = cp[d];
        float x = __bfloat162float(xp[d]);
        float z = aw * x + bg[d];
        float gate = 1.f / (1.f + __expf(-z));
        float o = gate * (aw * c) + (1.f - gate) * c;
        ov[i] = o;
        s += o; sq += o*o;
    }
    __shared__ float rs[4], rq[4];
    #pragma unroll
    for (int off = 16; off > 0; off >>= 1) {
        s  += __shfl_xor_sync(0xffffffffu, s, off);
        sq += __shfl_xor_sync(0xffffffffu, sq, off);
    }
    if ((tid & 31) == 0) { rs[tid >> 5] = s; rq[tid >> 5] = sq; }
    __syncthreads();
    float ts = rs[0] + rs[1] + rs[2] + rs[3];
    float tq = rq[0] + rq[1] + rq[2] + rq[3];
    float mu = ts / DMODEL;
    float var = tq / DMODEL - mu*mu;
    float inv = rsqrtf(var + 1e-5f);
    float* op = out + (size_t)row*DMODEL;
    #pragma unroll
    for (int i = 0; i < 5; i++) {
        int d = tid + i*128;
        op[d] = (ov[i] - mu) * inv * gamma[d] + beta[d];
    }
}

extern "C" void kernel_launch(void* const* d_in, const int* in_sizes, int n_in,
                              void* d_out, int out_size)
{
    const float* clicked_news   = (const float*)d_in[0];
    const float* clicked_topics = (const float*)d_in[1];
    const float* cand_topics    = (const float*)d_in[2];
    const float* Wq = (const float*)d_in[3];
    const float* bq = (const float*)d_in[4];
    const float* Wk = (const float*)d_in[5];
    const float* bk = (const float*)d_in[6];
    const float* Wg = (const float*)d_in[9];
    const float* bg = (const float*)d_in[10];
    const float* ln_gamma = (const float*)d_in[11];
    const float* ln_beta  = (const float*)d_in[12];
    float* out = (float*)d_out;

    cudaFuncSetAttribute(gemm_bf16<true>,  cudaFuncAttributeMaxDynamicSharedMemorySize, GEMM_SMEM);
    cudaFuncSetAttribute(gemm_bf16<false>, cudaFuncAttributeMaxDynamicSharedMemorySize, GEMM_SMEM);
    cudaFuncSetAttribute(attn_kernel, cudaFuncAttributeMaxDynamicSharedMemorySize, ATTN_SMEM);

    __nv_bfloat16 *p_Anb, *p_Atb, *p_Acb, *p_Wkb, *p_Wqb, *p_Wgb, *p_Qbf, *p_Kbf, *p_X;
    cudaGetSymbolAddress((void**)&p_Anb, g_Anb);
    cudaGetSymbolAddress((void**)&p_Atb, g_Atb);
    cudaGetSymbolAddress((void**)&p_Acb, g_Acb);
    cudaGetSymbolAddress((void**)&p_Wkb, g_Wkb);
    cudaGetSymbolAddress((void**)&p_Wqb, g_Wqb);
    cudaGetSymbolAddress((void**)&p_Wgb, g_Wgb);
    cudaGetSymbolAddress((void**)&p_Qbf, g_Qbf);
    cudaGetSymbolAddress((void**)&p_Kbf, g_Kbf);
    cudaGetSymbolAddress((void**)&p_X,   g_X);

    f2bf_kernel<<<32000, 256>>>(clicked_news,   p_Anb, MROWS_K*DMODEL);
    f2bf_kernel<<<12800, 256>>>(clicked_topics, p_Atb, MROWS_K*256);
    f2bf_kernel<<<4096,  256>>>(cand_topics,    p_Acb, MROWS_Q*256);
    f2bfw_kernel<<<512, 256>>>(Wk, p_Wkb, DMODEL*256, Wq, p_Wqb, DMODEL*256, Wg, p_Wgb, DMODEL*DMODEL);

    gemm_bf16<true><<<dim3(5, MROWS_K/128), 256, GEMM_SMEM>>>(p_Atb, p_Wkb, bk, p_Kbf, 256);
    gemm_bf16<false><<<dim3(5, MROWS_K/128), 256, GEMM_SMEM>>>(p_Anb, p_Wgb, nullptr, p_X, DMODEL);
    gemm_bf16<true><<<dim3(5, MROWS_Q/128), 256, GEMM_SMEM>>>(p_Acb, p_Wqb, bq, p_Qbf, 256);

    qw_kernel<<<BATCH, 256>>>();
    attn_kernel<<<dim3(NHEADS, BATCH), 128, ATTN_SMEM>>>();
    aggsm_kernel<<<BATCH, 256>>>(out + (size_t)MROWS_K*DMODEL);
    epilogue_kernel<<<MROWS_K, 128>>>(clicked_news, bg, ln_gamma, ln_beta, out);
}